// round 13
// baseline (speedup 1.0000x reference)
#include <cuda_runtime.h>
#include <cuda_bf16.h>
#include <math.h>
#include <stdint.h>

// Problem constants
#define Nn   20000
#define Ee   320000
#define Pp   50000
#define Ll   20
#define INF  128
#define HD   64
#define NEe  (Ee + Nn)
#define NC   384

// ---------------- device scratch ----------------
__device__ float g_H[Nn * HD];
__device__ float g_H0[Nn * HD];
__device__ __nv_bfloat16 g_dHall[(size_t)Ll * Nn * HD];  // dH slabs, bf16
__device__ float g_tau[(size_t)Ll * Pp];
__device__ float g_anti[Nn * HD];                 // anti_pre (cols 0-63), fp32 compact
__device__ __nv_bfloat16 g_Mb[Nn * HD];           // M (cols 64-127), bf16 compact
__device__ __nv_bfloat16 g_UV[(size_t)Nn * 256];  // U|V (cols 128-383), bf16 compact
__device__ float g_T[(size_t)Pp * HD];            // final T
__device__ __nv_bfloat16 g_Hhi[Nn * HD];
__device__ __nv_bfloat16 g_Hlo[Nn * HD];
__device__ __nv_bfloat16 g_Bhi[NC * HD];
__device__ __nv_bfloat16 g_Blo[NC * HD];
__device__ __nv_bfloat16 g_Wehi[HD * INF];
__device__ __nv_bfloat16 g_Welo[HD * INF];
__device__ __nv_bfloat16 g_Wp1hi[HD * INF];
__device__ __nv_bfloat16 g_Wp1lo[HD * INF];
__device__ __nv_bfloat16 g_rhi[(size_t)Pp * 2 * HD];
__device__ __nv_bfloat16 g_rlo[(size_t)Pp * 2 * HD];
__device__ float g_a[2][Nn];
__device__ float g_b[2][Nn];
__device__ int   g_deg[Nn];
__device__ float g_dinv[Nn];
__device__ int   g_off[Nn + 1];
__device__ int   g_fill[Nn];
__device__ int   g_csr_row[NEe];
__device__ float g_csr_norm[NEe];
__device__ int   g_hist[256];
__device__ int   g_binoff[256];
__device__ int   g_binfill[256];
__device__ int   g_nperm[Nn];

// ---------------- HMMA primitive ----------------
__device__ __forceinline__ void hmma(float* d, uint32_t a0, uint32_t a1,
                                     uint32_t a2, uint32_t a3,
                                     uint32_t b0, uint32_t b1) {
    asm volatile(
        "mma.sync.aligned.m16n8k16.row.col.f32.bf16.bf16.f32 "
        "{%0,%1,%2,%3}, {%4,%5,%6,%7}, {%8,%9}, {%0,%1,%2,%3};\n"
        : "+f"(d[0]), "+f"(d[1]), "+f"(d[2]), "+f"(d[3])
        : "r"(a0), "r"(a1), "r"(a2), "r"(a3), "r"(b0), "r"(b1));
}

// ---------------- loop step GEMM: anti/Mb/UV = H @ Bpacked (bf16x3) ----------------
#define S_AHI 0
#define S_ALO 18432
#define S_BHI 36864
#define S_BLO (36864 + 27648)
#define S_TOT (S_BLO + 27648)

__global__ __launch_bounds__(512, 1) void mma_step(
    const __nv_bfloat16* __restrict__ Ahi, const __nv_bfloat16* __restrict__ Alo) {
    extern __shared__ char sm[];
    const int tid = threadIdx.x;
    const int brow = blockIdx.x * 128;
    const int bcol = blockIdx.y * 192;

#pragma unroll
    for (int i = 0; i < 2; i++) {
        int idx = tid * 2 + i;
        int r = idx >> 3, c = idx & 7;
        int gr = brow + r;
        uint4 vh = make_uint4(0, 0, 0, 0), vl = make_uint4(0, 0, 0, 0);
        if (gr < Nn) {
            vh = *reinterpret_cast<const uint4*>(&Ahi[(size_t)gr * HD + c * 8]);
            vl = *reinterpret_cast<const uint4*>(&Alo[(size_t)gr * HD + c * 8]);
        }
        *reinterpret_cast<uint4*>(sm + S_AHI + r * 144 + c * 16) = vh;
        *reinterpret_cast<uint4*>(sm + S_ALO + r * 144 + c * 16) = vl;
    }
#pragma unroll
    for (int i = 0; i < 3; i++) {
        int idx = tid * 3 + i;
        int r = idx >> 3, c = idx & 7;
        *reinterpret_cast<uint4*>(sm + S_BHI + r * 144 + c * 16) =
            *reinterpret_cast<const uint4*>(&g_Bhi[(size_t)(bcol + r) * HD + c * 8]);
        *reinterpret_cast<uint4*>(sm + S_BLO + r * 144 + c * 16) =
            *reinterpret_cast<const uint4*>(&g_Blo[(size_t)(bcol + r) * HD + c * 8]);
    }
    __syncthreads();

    const int wid = tid >> 5, lane = tid & 31;
    const int wm = wid >> 2, wn = wid & 3;
    const int g = lane >> 2, t = lane & 3;

    float acc[2][6][4];
#pragma unroll
    for (int mt = 0; mt < 2; mt++)
#pragma unroll
        for (int nt = 0; nt < 6; nt++)
#pragma unroll
            for (int q = 0; q < 4; q++) acc[mt][nt][q] = 0.f;

#pragma unroll
    for (int ab = 0; ab < 3; ab++) {
        const char* Ab = sm + ((ab == 2) ? S_ALO : S_AHI);
        const char* Bb = sm + ((ab == 1) ? S_BLO : S_BHI);
#pragma unroll
        for (int kc = 0; kc < 4; kc++) {
            int kb = kc * 32 + t * 4;
            uint32_t bf[6][2];
#pragma unroll
            for (int nt = 0; nt < 6; nt++) {
                int nr = wn * 48 + nt * 8 + g;
                bf[nt][0] = *reinterpret_cast<const uint32_t*>(Bb + nr * 144 + kb);
                bf[nt][1] = *reinterpret_cast<const uint32_t*>(Bb + nr * 144 + kb + 16);
            }
#pragma unroll
            for (int mt = 0; mt < 2; mt++) {
                int r0 = wm * 32 + mt * 16 + g;
                uint32_t a0 = *reinterpret_cast<const uint32_t*>(Ab + r0 * 144 + kb);
                uint32_t a1 = *reinterpret_cast<const uint32_t*>(Ab + (r0 + 8) * 144 + kb);
                uint32_t a2 = *reinterpret_cast<const uint32_t*>(Ab + r0 * 144 + kb + 16);
                uint32_t a3 = *reinterpret_cast<const uint32_t*>(Ab + (r0 + 8) * 144 + kb + 16);
#pragma unroll
                for (int nt = 0; nt < 6; nt++)
                    hmma(acc[mt][nt], a0, a1, a2, a3, bf[nt][0], bf[nt][1]);
            }
        }
    }

    // epilogue split: anti fp32 / M bf16 / UV bf16
#pragma unroll
    for (int mt = 0; mt < 2; mt++) {
#pragma unroll
        for (int nt = 0; nt < 6; nt++) {
            int col = bcol + wn * 48 + nt * 8 + 2 * t;
#pragma unroll
            for (int h = 0; h < 2; h++) {
                int row = brow + wm * 32 + mt * 16 + g + h * 8;
                if (row >= Nn) continue;
                float v0 = acc[mt][nt][2 * h], v1 = acc[mt][nt][2 * h + 1];
                if (col < 64) {
                    *reinterpret_cast<float2*>(&g_anti[row * HD + col]) = make_float2(v0, v1);
                } else if (col < 128) {
                    __nv_bfloat162 v; v.x = __float2bfloat16(v0); v.y = __float2bfloat16(v1);
                    *reinterpret_cast<__nv_bfloat162*>(&g_Mb[row * HD + col - 64]) = v;
                } else {
                    __nv_bfloat162 v; v.x = __float2bfloat16(v0); v.y = __float2bfloat16(v1);
                    *reinterpret_cast<__nv_bfloat162*>(&g_UV[(size_t)row * 256 + col - 128]) = v;
                }
            }
        }
    }
}

// ---------------- generic HMMA GEMM, N=64 (optional fp32 A with in-kernel split) ----------------
__global__ __launch_bounds__(512, 1) void mma_gemm64(
    const float* __restrict__ Afp,
    const __nv_bfloat16* __restrict__ Ahi, const __nv_bfloat16* __restrict__ Alo,
    const __nv_bfloat16* __restrict__ Bhi, const __nv_bfloat16* __restrict__ Blo,
    float* __restrict__ C, int M, int K, int act) {
    extern __shared__ char sm[];
    const int tid = threadIdx.x;
    const int brow = blockIdx.x * 128;
    const int SB = K * 2 + 16;
    char* Ah = sm;
    char* Al = sm + 128 * SB;
    char* Bh = sm + 256 * SB;
    char* Bl = sm + 320 * SB;
    const int ku4 = K >> 3;

    for (int idx = tid; idx < 128 * ku4; idx += 512) {
        int r = idx / ku4, c = idx % ku4;
        int gr = brow + r;
        uint4 vh = make_uint4(0, 0, 0, 0), vl = make_uint4(0, 0, 0, 0);
        if (gr < M) {
            if (Afp) {
                const float* src = &Afp[(size_t)gr * K + c * 8];
                float4 f0 = *reinterpret_cast<const float4*>(src);
                float4 f1 = *reinterpret_cast<const float4*>(src + 4);
                float fs[8] = {f0.x, f0.y, f0.z, f0.w, f1.x, f1.y, f1.z, f1.w};
                __nv_bfloat16 hs[8], ls[8];
#pragma unroll
                for (int q = 0; q < 8; q++) {
                    hs[q] = __float2bfloat16(fs[q]);
                    ls[q] = __float2bfloat16(fs[q] - __bfloat162float(hs[q]));
                }
                vh = *reinterpret_cast<uint4*>(hs);
                vl = *reinterpret_cast<uint4*>(ls);
            } else {
                vh = *reinterpret_cast<const uint4*>(&Ahi[(size_t)gr * K + c * 8]);
                vl = *reinterpret_cast<const uint4*>(&Alo[(size_t)gr * K + c * 8]);
            }
        }
        *reinterpret_cast<uint4*>(Ah + r * SB + c * 16) = vh;
        *reinterpret_cast<uint4*>(Al + r * SB + c * 16) = vl;
    }
    for (int idx = tid; idx < 64 * ku4; idx += 512) {
        int r = idx / ku4, c = idx % ku4;
        *reinterpret_cast<uint4*>(Bh + r * SB + c * 16) =
            *reinterpret_cast<const uint4*>(&Bhi[(size_t)r * K + c * 8]);
        *reinterpret_cast<uint4*>(Bl + r * SB + c * 16) =
            *reinterpret_cast<const uint4*>(&Blo[(size_t)r * K + c * 8]);
    }
    __syncthreads();

    const int wid = tid >> 5, lane = tid & 31;
    const int wm = wid >> 2, wn = wid & 3;
    const int g = lane >> 2, t = lane & 3;
    const int KC = K >> 4;

    float acc[2][2][4];
#pragma unroll
    for (int mt = 0; mt < 2; mt++)
#pragma unroll
        for (int nt = 0; nt < 2; nt++)
#pragma unroll
            for (int q = 0; q < 4; q++) acc[mt][nt][q] = 0.f;

#pragma unroll
    for (int ab = 0; ab < 3; ab++) {
        const char* A_ = (ab == 2) ? Al : Ah;
        const char* B_ = (ab == 1) ? Bl : Bh;
        for (int kc = 0; kc < KC; kc++) {
            int kb = kc * 32 + t * 4;
            uint32_t bf[2][2];
#pragma unroll
            for (int nt = 0; nt < 2; nt++) {
                int nr = wn * 16 + nt * 8 + g;
                bf[nt][0] = *reinterpret_cast<const uint32_t*>(B_ + nr * SB + kb);
                bf[nt][1] = *reinterpret_cast<const uint32_t*>(B_ + nr * SB + kb + 16);
            }
#pragma unroll
            for (int mt = 0; mt < 2; mt++) {
                int r0 = wm * 32 + mt * 16 + g;
                uint32_t a0 = *reinterpret_cast<const uint32_t*>(A_ + r0 * SB + kb);
                uint32_t a1 = *reinterpret_cast<const uint32_t*>(A_ + (r0 + 8) * SB + kb);
                uint32_t a2 = *reinterpret_cast<const uint32_t*>(A_ + r0 * SB + kb + 16);
                uint32_t a3 = *reinterpret_cast<const uint32_t*>(A_ + (r0 + 8) * SB + kb + 16);
#pragma unroll
                for (int nt = 0; nt < 2; nt++)
                    hmma(acc[mt][nt], a0, a1, a2, a3, bf[nt][0], bf[nt][1]);
            }
        }
    }

#pragma unroll
    for (int mt = 0; mt < 2; mt++) {
#pragma unroll
        for (int nt = 0; nt < 2; nt++) {
            int row = brow + wm * 32 + mt * 16 + g;
            int col = wn * 16 + nt * 8 + 2 * t;
            float v0 = acc[mt][nt][0], v1 = acc[mt][nt][1];
            float v2 = acc[mt][nt][2], v3 = acc[mt][nt][3];
            if (act) {
                v0 = fmaxf(v0, 0.f); v1 = fmaxf(v1, 0.f);
                v2 = fmaxf(v2, 0.f); v3 = fmaxf(v3, 0.f);
            }
            if (row < M)
                *reinterpret_cast<float2*>(&C[(size_t)row * 64 + col]) = make_float2(v0, v1);
            if (row + 8 < M)
                *reinterpret_cast<float2*>(&C[(size_t)(row + 8) * 64 + col]) = make_float2(v2, v3);
        }
    }
}

// ---------------- weight packing ----------------
__global__ void k_prepB(const float* __restrict__ Om, const float* __restrict__ Ws,
                        const float* __restrict__ Wfc1) {
    int i = blockIdx.x * blockDim.x + threadIdx.x;
    if (i >= HD * NC) return;
    int k = i / NC, j = i % NC;
    float v;
    if (j < 64)       v = Om[k * 64 + j] - Om[j * 64 + k];
    else if (j < 128) { int jj = j - 64; v = 0.5f * (Ws[k * 64 + jj] + Ws[jj * 64 + k]); }
    else if (j < 256) v = Wfc1[k * 128 + (j - 128)];
    else              v = Wfc1[(64 + k) * 128 + (j - 256)];
    __nv_bfloat16 hi = __float2bfloat16(v);
    __nv_bfloat16 lo = __float2bfloat16(v - __bfloat162float(hi));
    g_Bhi[(size_t)j * HD + k] = hi;
    g_Blo[(size_t)j * HD + k] = lo;
}

__global__ void k_prepW(const float* __restrict__ src, int K,
                        __nv_bfloat16* __restrict__ dhi, __nv_bfloat16* __restrict__ dlo) {
    int i = blockIdx.x * blockDim.x + threadIdx.x;
    if (i >= K * HD) return;
    int k = i / HD, n = i % HD;
    float v = src[i];
    __nv_bfloat16 hi = __float2bfloat16(v);
    dhi[(size_t)n * K + k] = hi;
    dlo[(size_t)n * K + k] = __float2bfloat16(v - __bfloat162float(hi));
}

// ---------------- graph preprocessing ----------------
__global__ void k_init() {
    int i = blockIdx.x * blockDim.x + threadIdx.x;
    if (i < Nn) { g_deg[i] = 1; g_fill[i] = 0; }
    if (i < 256) { g_hist[i] = 0; g_binfill[i] = 0; }
}

__global__ void k_deg(const int* __restrict__ ei) {
    int e = blockIdx.x * blockDim.x + threadIdx.x;
    if (e < Ee) atomicAdd(&g_deg[ei[Ee + e]], 1);
}

__global__ void k_dinv() {
    int n = blockIdx.x * blockDim.x + threadIdx.x;
    if (n < Nn) g_dinv[n] = rsqrtf((float)g_deg[n]);
}

__global__ void k_scan() {
    __shared__ int sh[1024];
    __shared__ int carry_s;
    int t = threadIdx.x;
    if (t == 0) carry_s = 0;
    __syncthreads();
    for (int base = 0; base < Nn; base += 1024) {
        int v = (base + t < Nn) ? g_deg[base + t] : 0;
        int x = v;
        for (int off = 1; off < 1024; off <<= 1) {
            sh[t] = x; __syncthreads();
            if (t >= off) x += sh[t - off];
            __syncthreads();
        }
        int carry = carry_s;
        if (base + t < Nn) g_off[base + t] = carry + x - v;
        __syncthreads();
        if (t == 1023) carry_s = carry + x;
        __syncthreads();
    }
    if (t == 0) g_off[Nn] = carry_s;
}

__global__ void k_fill(const int* __restrict__ ei) {
    int e = blockIdx.x * blockDim.x + threadIdx.x;
    if (e >= NEe) return;
    int r_, c_;
    if (e < Ee) { r_ = ei[e]; c_ = ei[Ee + e]; }
    else        { r_ = c_ = e - Ee; }
    int pos = g_off[c_] + atomicAdd(&g_fill[c_], 1);
    g_csr_row[pos]  = r_;
    g_csr_norm[pos] = g_dinv[r_] * g_dinv[c_];
}

// degree histogram (bin = 255 - clamped deg -> descending order)
__global__ void k_hist() {
    int n = blockIdx.x * blockDim.x + threadIdx.x;
    if (n >= Nn) return;
    int d = g_deg[n]; if (d > 255) d = 255;
    atomicAdd(&g_hist[255 - d], 1);
}

__global__ void k_binscan() {   // 1 thread: 256 iterations, trivial
    if (threadIdx.x == 0) {
        int acc = 0;
        for (int i = 0; i < 256; i++) { g_binoff[i] = acc; acc += g_hist[i]; }
    }
}

__global__ void k_scatter() {
    int n = blockIdx.x * blockDim.x + threadIdx.x;
    if (n >= Nn) return;
    int d = g_deg[n]; if (d > 255) d = 255;
    int bin = 255 - d;
    int pos = g_binoff[bin] + atomicAdd(&g_binfill[bin], 1);
    g_nperm[pos] = n;
}

// H snapshot + bf16 split + a,b for step 0 (fused)
__global__ __launch_bounds__(256) void k_h2b_ab(const float* __restrict__ Wfv) {
    int warp = (blockIdx.x * blockDim.x + threadIdx.x) >> 5;
    int lane = threadIdx.x & 31;
    if (warp >= Nn) return;
    int n = warp;
    float h0 = g_H[n * HD + lane], h1 = g_H[n * HD + lane + 32];
    g_H0[n * HD + lane] = h0;
    g_H0[n * HD + lane + 32] = h1;
    __nv_bfloat16 hi0 = __float2bfloat16(h0);
    __nv_bfloat16 hi1 = __float2bfloat16(h1);
    g_Hhi[n * HD + lane]      = hi0;
    g_Hhi[n * HD + lane + 32] = hi1;
    g_Hlo[n * HD + lane]      = __float2bfloat16(h0 - __bfloat162float(hi0));
    g_Hlo[n * HD + lane + 32] = __float2bfloat16(h1 - __bfloat162float(hi1));
    float pa = h0 * Wfv[lane]      + h1 * Wfv[lane + 32];
    float pb = h0 * Wfv[64 + lane] + h1 * Wfv[96 + lane];
#pragma unroll
    for (int o = 16; o > 0; o >>= 1) {
        pa += __shfl_xor_sync(0xffffffffu, pa, o);
        pb += __shfl_xor_sync(0xffffffffu, pb, o);
    }
    if (lane == 0) { g_a[0][n] = pa; g_b[0][n] = pb; }
}

// ---------------- fused per-step kernel ----------------
// node path: warp w handles n = g_nperm[w] (degree-descending), lane -> cols (2l, 2l+1)
__global__ __launch_bounds__(256) void k_step(const int* __restrict__ pairs,
                                              const float* __restrict__ gum,
                                              const float* __restrict__ Wfc2,
                                              const float* __restrict__ Wfv,
                                              int l) {
    int warp = (blockIdx.x * blockDim.x + threadIdx.x) >> 5;
    int lane = threadIdx.x & 31;
    if (warp < Nn) {
        int n = g_nperm[warp];
        int c2 = 2 * lane;
        int beg = g_off[n], end = g_off[n + 1];
        float s0 = 0.f, s1 = 0.f;
        int i = beg;
        for (; i + 3 < end; i += 4) {
            int ra = __ldg(&g_csr_row[i]);
            int rb = __ldg(&g_csr_row[i + 1]);
            int rc = __ldg(&g_csr_row[i + 2]);
            int rd = __ldg(&g_csr_row[i + 3]);
            float wa = __ldg(&g_csr_norm[i]);
            float wb = __ldg(&g_csr_norm[i + 1]);
            float wc = __ldg(&g_csr_norm[i + 2]);
            float wd = __ldg(&g_csr_norm[i + 3]);
            uint32_t ua = __ldg(reinterpret_cast<const uint32_t*>(&g_Mb[ra * HD + c2]));
            uint32_t ub = __ldg(reinterpret_cast<const uint32_t*>(&g_Mb[rb * HD + c2]));
            uint32_t uc = __ldg(reinterpret_cast<const uint32_t*>(&g_Mb[rc * HD + c2]));
            uint32_t ud = __ldg(reinterpret_cast<const uint32_t*>(&g_Mb[rd * HD + c2]));
            __nv_bfloat162 va = *reinterpret_cast<__nv_bfloat162*>(&ua);
            __nv_bfloat162 vb = *reinterpret_cast<__nv_bfloat162*>(&ub);
            __nv_bfloat162 vc = *reinterpret_cast<__nv_bfloat162*>(&uc);
            __nv_bfloat162 vd = *reinterpret_cast<__nv_bfloat162*>(&ud);
            s0 += __bfloat162float(va.x) * wa + __bfloat162float(vb.x) * wb
                + __bfloat162float(vc.x) * wc + __bfloat162float(vd.x) * wd;
            s1 += __bfloat162float(va.y) * wa + __bfloat162float(vb.y) * wb
                + __bfloat162float(vc.y) * wc + __bfloat162float(vd.y) * wd;
        }
        for (; i < end; i++) {
            int rs = __ldg(&g_csr_row[i]);
            float w = __ldg(&g_csr_norm[i]);
            uint32_t u = __ldg(reinterpret_cast<const uint32_t*>(&g_Mb[rs * HD + c2]));
            __nv_bfloat162 v = *reinterpret_cast<__nv_bfloat162*>(&u);
            s0 += __bfloat162float(v.x) * w;
            s1 += __bfloat162float(v.y) * w;
        }
        float2 av = *reinterpret_cast<const float2*>(&g_anti[n * HD + c2]);
        float dh0 = fmaxf(tanhf(s0 - fmaxf(av.x, 0.f)), 0.f);
        float dh1 = fmaxf(tanhf(s1 - fmaxf(av.y, 0.f)), 0.f);
        __nv_bfloat162 dv;
        dv.x = __float2bfloat16(dh0);
        dv.y = __float2bfloat16(dh1);
        *reinterpret_cast<__nv_bfloat162*>(&g_dHall[(size_t)l * Nn * HD + n * HD + c2]) = dv;
        float2 hv = *reinterpret_cast<const float2*>(&g_H[n * HD + c2]);
        float hn0 = hv.x + dh0;
        float hn1 = hv.y + dh1;
        *reinterpret_cast<float2*>(&g_H[n * HD + c2]) = make_float2(hn0, hn1);
        __nv_bfloat16 hi0 = __float2bfloat16(hn0);
        __nv_bfloat16 hi1 = __float2bfloat16(hn1);
        __nv_bfloat162 hiv; hiv.x = hi0; hiv.y = hi1;
        __nv_bfloat162 lov;
        lov.x = __float2bfloat16(hn0 - __bfloat162float(hi0));
        lov.y = __float2bfloat16(hn1 - __bfloat162float(hi1));
        *reinterpret_cast<__nv_bfloat162*>(&g_Hhi[n * HD + c2]) = hiv;
        *reinterpret_cast<__nv_bfloat162*>(&g_Hlo[n * HD + c2]) = lov;
        float pa = hn0 * Wfv[c2]      + hn1 * Wfv[c2 + 1];
        float pb = hn0 * Wfv[64 + c2] + hn1 * Wfv[64 + c2 + 1];
#pragma unroll
        for (int o = 16; o > 0; o >>= 1) {
            pa += __shfl_xor_sync(0xffffffffu, pa, o);
            pb += __shfl_xor_sync(0xffffffffu, pb, o);
        }
        if (lane == 0) { g_a[(l + 1) & 1][n] = pa; g_b[(l + 1) & 1][n] = pb; }
    } else {
        // ---- pair path: bf16 U/V ----
        int p = warp - Nn;
        if (p >= Pp) return;
        int s = pairs[2 * p], d = pairs[2 * p + 1];
        const __nv_bfloat16* Us = &g_UV[(size_t)s * 256];
        const __nv_bfloat16* Vd = &g_UV[(size_t)d * 256 + 128];
        float l0 = 0.f, l1 = 0.f;
#pragma unroll
        for (int h = 0; h < 2; h++) {
            int c = 64 * h + 2 * lane;
            uint32_t uu = __ldg(reinterpret_cast<const uint32_t*>(&Us[c]));
            uint32_t vv = __ldg(reinterpret_cast<const uint32_t*>(&Vd[c]));
            __nv_bfloat162 ub = *reinterpret_cast<__nv_bfloat162*>(&uu);
            __nv_bfloat162 vb = *reinterpret_cast<__nv_bfloat162*>(&vv);
            float h0 = fmaxf(__bfloat162float(ub.x) + __bfloat162float(vb.x), 0.f);
            float h1 = fmaxf(__bfloat162float(ub.y) + __bfloat162float(vb.y), 0.f);
            l0 += h0 * Wfc2[2 * c]     + h1 * Wfc2[2 * (c + 1)];
            l1 += h0 * Wfc2[2 * c + 1] + h1 * Wfc2[2 * (c + 1) + 1];
        }
#pragma unroll
        for (int o = 16; o > 0; o >>= 1) {
            l0 += __shfl_xor_sync(0xffffffffu, l0, o);
            l1 += __shfl_xor_sync(0xffffffffu, l1, o);
        }
        if (lane == 0) {
            int ph = l & 1;
            float z  = g_a[ph][s] + g_b[ph][d];
            float nu = fmaxf(z, 0.f) + log1pf(expf(-fabsf(z))) + 1.0f;
            float g0 = __ldg(&gum[((size_t)l * Pp + p) * 2]);
            float g1 = __ldg(&gum[((size_t)l * Pp + p) * 2 + 1]);
            float diff = ((l1 + g1) - (l0 + g0)) / nu;
            g_tau[(size_t)l * Pp + p] = 1.f / (1.f + expf(diff));
        }
    }
}

// ---------------- final: assemble r -> bf16 hi/lo, write ts ----------------
__global__ __launch_bounds__(256) void k_final(const int* __restrict__ pairs,
                                               float* __restrict__ out) {
    int warp = (blockIdx.x * blockDim.x + threadIdx.x) >> 5;
    int lane = threadIdx.x & 31;
    if (warp >= Pp) return;
    int p = warp;
    int s = pairs[2 * p], d = pairs[2 * p + 1];
    float2 hs = *reinterpret_cast<const float2*>(&g_H0[s * HD + 2 * lane]);
    float2 hd = *reinterpret_cast<const float2*>(&g_H0[d * HD + 2 * lane]);
    float r0 = hs.x, r1 = hs.y;
    float r2 = hd.x, r3 = hd.y;
    float tval = (lane < Ll) ? g_tau[(size_t)lane * Pp + p] : 0.f;
    float ts = 0.f;
#pragma unroll
    for (int l = 0; l < Ll; l++) {
        float tau = __shfl_sync(0xffffffffu, tval, l);
        const __nv_bfloat16* slab = &g_dHall[(size_t)l * Nn * HD];
        __nv_bfloat162 ds = *reinterpret_cast<const __nv_bfloat162*>(&slab[s * HD + 2 * lane]);
        __nv_bfloat162 dd = *reinterpret_cast<const __nv_bfloat162*>(&slab[d * HD + 2 * lane]);
        r0 += tau * __bfloat162float(ds.x);
        r1 += tau * __bfloat162float(ds.y);
        r2 += tau * __bfloat162float(dd.x);
        r3 += tau * __bfloat162float(dd.y);
        ts += tau;
    }
    size_t base = (size_t)p * 2 * HD;
    __nv_bfloat16 h0 = __float2bfloat16(r0);
    __nv_bfloat16 h1 = __float2bfloat16(r1);
    __nv_bfloat16 h2 = __float2bfloat16(r2);
    __nv_bfloat16 h3 = __float2bfloat16(r3);
    __nv_bfloat162 lo01, lo23;
    lo01.x = __float2bfloat16(r0 - __bfloat162float(h0));
    lo01.y = __float2bfloat16(r1 - __bfloat162float(h1));
    lo23.x = __float2bfloat16(r2 - __bfloat162float(h2));
    lo23.y = __float2bfloat16(r3 - __bfloat162float(h3));
    __nv_bfloat162 hi01; hi01.x = h0; hi01.y = h1;
    __nv_bfloat162 hi23; hi23.x = h2; hi23.y = h3;
    *reinterpret_cast<__nv_bfloat162*>(&g_rhi[base + 2 * lane]) = hi01;
    *reinterpret_cast<__nv_bfloat162*>(&g_rhi[base + HD + 2 * lane]) = hi23;
    *reinterpret_cast<__nv_bfloat162*>(&g_rlo[base + 2 * lane]) = lo01;
    *reinterpret_cast<__nv_bfloat162*>(&g_rlo[base + HD + 2 * lane]) = lo23;
    if (lane == 0) out[Pp + p] = ts;
}

// ---------------- final scores ----------------
__global__ __launch_bounds__(256) void k_score(const float* __restrict__ Wp2,
                                               float* __restrict__ out) {
    int warp = (blockIdx.x * blockDim.x + threadIdx.x) >> 5;
    int lane = threadIdx.x & 31;
    if (warp >= Pp) return;
    int p = warp;
    float t0 = g_T[(size_t)p * 64 + 2 * lane];
    float t1 = g_T[(size_t)p * 64 + 2 * lane + 1];
    float acc = t0 * Wp2[2 * lane] + t1 * Wp2[2 * lane + 1];
#pragma unroll
    for (int o = 16; o > 0; o >>= 1) acc += __shfl_xor_sync(0xffffffffu, acc, o);
    if (lane == 0) out[p] = acc;
}

// ---------------- host ----------------
extern "C" void kernel_launch(void* const* d_in, const int* in_sizes, int n_in,
                              void* d_out, int out_size) {
    const float* x    = (const float*)d_in[0];
    const int*   ei   = (const int*)d_in[1];
    const int*   pairs= (const int*)d_in[2];
    const float* gum  = (const float*)d_in[3];
    const float* Wenc = (const float*)d_in[4];
    const float* Om   = (const float*)d_in[5];
    const float* Wsr  = (const float*)d_in[6];
    const float* Wfc1 = (const float*)d_in[7];
    const float* Wfc2 = (const float*)d_in[8];
    const float* Wfv  = (const float*)d_in[9];
    const float* Wp1  = (const float*)d_in[10];
    const float* Wp2  = (const float*)d_in[11];
    float* out = (float*)d_out;

    void *pH, *pT, *pHhi, *pHlo, *pWeh, *pWel, *pWph, *pWpl, *pRhi, *pRlo;
    cudaGetSymbolAddress(&pH, g_H);
    cudaGetSymbolAddress(&pT, g_T);
    cudaGetSymbolAddress(&pHhi, g_Hhi);
    cudaGetSymbolAddress(&pHlo, g_Hlo);
    cudaGetSymbolAddress(&pWeh, g_Wehi);
    cudaGetSymbolAddress(&pWel, g_Welo);
    cudaGetSymbolAddress(&pWph, g_Wp1hi);
    cudaGetSymbolAddress(&pWpl, g_Wp1lo);
    cudaGetSymbolAddress(&pRhi, g_rhi);
    cudaGetSymbolAddress(&pRlo, g_rlo);
    float* H_ = (float*)pH;
    float* T_ = (float*)pT;
    const __nv_bfloat16* Hhi_ = (const __nv_bfloat16*)pHhi;
    const __nv_bfloat16* Hlo_ = (const __nv_bfloat16*)pHlo;

    cudaFuncSetAttribute(mma_step, cudaFuncAttributeMaxDynamicSharedMemorySize, S_TOT);
    const int SM64 = 384 * (INF * 2 + 16);
    cudaFuncSetAttribute(mma_gemm64, cudaFuncAttributeMaxDynamicSharedMemorySize, SM64);

    // side stream for graph preprocessing — fork from capture stream
    cudaStream_t s1;
    cudaStreamCreateWithFlags(&s1, cudaStreamNonBlocking);
    cudaEvent_t evFork, evPrep;
    cudaEventCreateWithFlags(&evFork, cudaEventDisableTiming);
    cudaEventCreateWithFlags(&evPrep, cudaEventDisableTiming);

    cudaEventRecord(evFork, 0);
    cudaStreamWaitEvent(s1, evFork, 0);

    // ---- graph prep + degree sort on s1 ----
    k_init<<<(Nn + 255) / 256, 256, 0, s1>>>();
    k_deg<<<(Ee + 255) / 256, 256, 0, s1>>>(ei);
    k_dinv<<<(Nn + 255) / 256, 256, 0, s1>>>();
    k_scan<<<1, 1024, 0, s1>>>();
    k_fill<<<(NEe + 255) / 256, 256, 0, s1>>>(ei);
    k_hist<<<(Nn + 255) / 256, 256, 0, s1>>>();
    k_binscan<<<1, 32, 0, s1>>>();
    k_scatter<<<(Nn + 255) / 256, 256, 0, s1>>>();
    cudaEventRecord(evPrep, s1);

    // ---- dense prologue on stream 0 ----
    k_prepB<<<(HD * NC + 255) / 256, 256>>>(Om, Wsr, Wfc1);
    k_prepW<<<(INF * HD + 255) / 256, 256>>>(Wenc, INF, (__nv_bfloat16*)pWeh, (__nv_bfloat16*)pWel);
    k_prepW<<<(INF * HD + 255) / 256, 256>>>(Wp1, INF, (__nv_bfloat16*)pWph, (__nv_bfloat16*)pWpl);
    mma_gemm64<<<(Nn + 127) / 128, 512, SM64>>>(
        x, nullptr, nullptr,
        (const __nv_bfloat16*)pWeh, (const __nv_bfloat16*)pWel, H_, Nn, INF, 1);
    k_h2b_ab<<<(Nn * 32 + 255) / 256, 256>>>(Wfv);

    dim3 grid_mma((Nn + 127) / 128, 2);
    int step_blocks = ((Nn + Pp) * 32 + 255) / 256;
    for (int l = 0; l < Ll; l++) {
        mma_step<<<grid_mma, 512, S_TOT>>>(Hhi_, Hlo_);
        if (l == 0) cudaStreamWaitEvent(0, evPrep, 0);
        k_step<<<step_blocks, 256>>>(pairs, gum, Wfc2, Wfv, l);
    }

    // r (bf16 hi/lo) + ts, then T = relu(r @ Wp1) via HMMA, then scores
    k_final<<<(Pp * 32 + 255) / 256, 256>>>(pairs, out);
    mma_gemm64<<<(Pp + 127) / 128, 512, SM64>>>(
        nullptr, (const __nv_bfloat16*)pRhi, (const __nv_bfloat16*)pRlo,
        (const __nv_bfloat16*)pWph, (const __nv_bfloat16*)pWpl, T_, Pp, INF, 1);
    k_score<<<(Pp * 32 + 255) / 256, 256>>>(Wp2, out);

    cudaStreamDestroy(s1);
    cudaEventDestroy(evFork);
    cudaEventDestroy(evPrep);
}

// round 14
// speedup vs baseline: 1.0543x; 1.0543x over previous
#include <cuda_runtime.h>
#include <cuda_bf16.h>
#include <math.h>
#include <stdint.h>

// Problem constants
#define Nn   20000
#define Ee   320000
#define Pp   50000
#define Ll   20
#define INF  128
#define HD   64
#define NEe  (Ee + Nn)
#define NC   384

// ---------------- device scratch ----------------
__device__ float g_H[Nn * HD];
__device__ float g_H0[Nn * HD];
__device__ __nv_bfloat16 g_dHall[(size_t)Ll * Nn * HD];  // dH slabs, bf16
__device__ float g_tau[(size_t)Ll * Pp];
__device__ float g_C[(size_t)Nn * NC];            // step GEMM out (anti/U/V); reused as T
__device__ __nv_bfloat16 g_Mb[Nn * HD];           // M block (cols 64-127) bf16 compact
__device__ __nv_bfloat16 g_Hhi[Nn * HD];
__device__ __nv_bfloat16 g_Hlo[Nn * HD];
__device__ __nv_bfloat16 g_Bhi[NC * HD];
__device__ __nv_bfloat16 g_Blo[NC * HD];
__device__ __nv_bfloat16 g_Wehi[HD * INF];
__device__ __nv_bfloat16 g_Welo[HD * INF];
__device__ __nv_bfloat16 g_Wp1hi[HD * INF];
__device__ __nv_bfloat16 g_Wp1lo[HD * INF];
__device__ __nv_bfloat16 g_rhi[(size_t)Pp * 2 * HD];
__device__ __nv_bfloat16 g_rlo[(size_t)Pp * 2 * HD];
__device__ float g_a[2][Nn];
__device__ float g_b[2][Nn];
__device__ int   g_deg[Nn];
__device__ float g_dinv[Nn];
__device__ int   g_off[Nn + 1];
__device__ int   g_fill[Nn];
__device__ int2  g_csrp[NEe];                     // packed {row, norm bits}

// ---------------- HMMA primitive ----------------
__device__ __forceinline__ void hmma(float* d, uint32_t a0, uint32_t a1,
                                     uint32_t a2, uint32_t a3,
                                     uint32_t b0, uint32_t b1) {
    asm volatile(
        "mma.sync.aligned.m16n8k16.row.col.f32.bf16.bf16.f32 "
        "{%0,%1,%2,%3}, {%4,%5,%6,%7}, {%8,%9}, {%0,%1,%2,%3};\n"
        : "+f"(d[0]), "+f"(d[1]), "+f"(d[2]), "+f"(d[3])
        : "r"(a0), "r"(a1), "r"(a2), "r"(a3), "r"(b0), "r"(b1));
}

// ---------------- loop step GEMM: C/Mb = H @ Bpacked (bf16x3) ----------------
#define S_AHI 0
#define S_ALO 18432
#define S_BHI 36864
#define S_BLO (36864 + 27648)
#define S_TOT (S_BLO + 27648)

__global__ __launch_bounds__(512, 1) void mma_step(
    const __nv_bfloat16* __restrict__ Ahi, const __nv_bfloat16* __restrict__ Alo) {
    extern __shared__ char sm[];
    const int tid = threadIdx.x;
    const int brow = blockIdx.x * 128;
    const int bcol = blockIdx.y * 192;

#pragma unroll
    for (int i = 0; i < 2; i++) {
        int idx = tid * 2 + i;
        int r = idx >> 3, c = idx & 7;
        int gr = brow + r;
        uint4 vh = make_uint4(0, 0, 0, 0), vl = make_uint4(0, 0, 0, 0);
        if (gr < Nn) {
            vh = *reinterpret_cast<const uint4*>(&Ahi[(size_t)gr * HD + c * 8]);
            vl = *reinterpret_cast<const uint4*>(&Alo[(size_t)gr * HD + c * 8]);
        }
        *reinterpret_cast<uint4*>(sm + S_AHI + r * 144 + c * 16) = vh;
        *reinterpret_cast<uint4*>(sm + S_ALO + r * 144 + c * 16) = vl;
    }
#pragma unroll
    for (int i = 0; i < 3; i++) {
        int idx = tid * 3 + i;
        int r = idx >> 3, c = idx & 7;
        *reinterpret_cast<uint4*>(sm + S_BHI + r * 144 + c * 16) =
            *reinterpret_cast<const uint4*>(&g_Bhi[(size_t)(bcol + r) * HD + c * 8]);
        *reinterpret_cast<uint4*>(sm + S_BLO + r * 144 + c * 16) =
            *reinterpret_cast<const uint4*>(&g_Blo[(size_t)(bcol + r) * HD + c * 8]);
    }
    __syncthreads();

    const int wid = tid >> 5, lane = tid & 31;
    const int wm = wid >> 2, wn = wid & 3;
    const int g = lane >> 2, t = lane & 3;

    float acc[2][6][4];
#pragma unroll
    for (int mt = 0; mt < 2; mt++)
#pragma unroll
        for (int nt = 0; nt < 6; nt++)
#pragma unroll
            for (int q = 0; q < 4; q++) acc[mt][nt][q] = 0.f;

#pragma unroll
    for (int ab = 0; ab < 3; ab++) {
        const char* Ab = sm + ((ab == 2) ? S_ALO : S_AHI);
        const char* Bb = sm + ((ab == 1) ? S_BLO : S_BHI);
#pragma unroll
        for (int kc = 0; kc < 4; kc++) {
            int kb = kc * 32 + t * 4;
            uint32_t bf[6][2];
#pragma unroll
            for (int nt = 0; nt < 6; nt++) {
                int nr = wn * 48 + nt * 8 + g;
                bf[nt][0] = *reinterpret_cast<const uint32_t*>(Bb + nr * 144 + kb);
                bf[nt][1] = *reinterpret_cast<const uint32_t*>(Bb + nr * 144 + kb + 16);
            }
#pragma unroll
            for (int mt = 0; mt < 2; mt++) {
                int r0 = wm * 32 + mt * 16 + g;
                uint32_t a0 = *reinterpret_cast<const uint32_t*>(Ab + r0 * 144 + kb);
                uint32_t a1 = *reinterpret_cast<const uint32_t*>(Ab + (r0 + 8) * 144 + kb);
                uint32_t a2 = *reinterpret_cast<const uint32_t*>(Ab + r0 * 144 + kb + 16);
                uint32_t a3 = *reinterpret_cast<const uint32_t*>(Ab + (r0 + 8) * 144 + kb + 16);
#pragma unroll
                for (int nt = 0; nt < 6; nt++)
                    hmma(acc[mt][nt], a0, a1, a2, a3, bf[nt][0], bf[nt][1]);
            }
        }
    }

    // epilogue: M cols (64..127) -> bf16 compact g_Mb; others -> fp32 g_C
#pragma unroll
    for (int mt = 0; mt < 2; mt++) {
#pragma unroll
        for (int nt = 0; nt < 6; nt++) {
            int row = brow + wm * 32 + mt * 16 + g;
            int col = bcol + wn * 48 + nt * 8 + 2 * t;
            bool isM = (col >= 64) && (col < 128);
            if (row < Nn) {
                if (isM) {
                    __nv_bfloat162 v;
                    v.x = __float2bfloat16(acc[mt][nt][0]);
                    v.y = __float2bfloat16(acc[mt][nt][1]);
                    *reinterpret_cast<__nv_bfloat162*>(&g_Mb[row * HD + col - 64]) = v;
                } else {
                    *reinterpret_cast<float2*>(&g_C[(size_t)row * NC + col]) =
                        make_float2(acc[mt][nt][0], acc[mt][nt][1]);
                }
            }
            if (row + 8 < Nn) {
                if (isM) {
                    __nv_bfloat162 v;
                    v.x = __float2bfloat16(acc[mt][nt][2]);
                    v.y = __float2bfloat16(acc[mt][nt][3]);
                    *reinterpret_cast<__nv_bfloat162*>(&g_Mb[(row + 8) * HD + col - 64]) = v;
                } else {
                    *reinterpret_cast<float2*>(&g_C[(size_t)(row + 8) * NC + col]) =
                        make_float2(acc[mt][nt][2], acc[mt][nt][3]);
                }
            }
        }
    }
}

// ---------------- generic HMMA GEMM, N=64 (optional fp32 A with in-kernel split) ----------------
__global__ __launch_bounds__(512, 1) void mma_gemm64(
    const float* __restrict__ Afp,
    const __nv_bfloat16* __restrict__ Ahi, const __nv_bfloat16* __restrict__ Alo,
    const __nv_bfloat16* __restrict__ Bhi, const __nv_bfloat16* __restrict__ Blo,
    float* __restrict__ C, int M, int K, int act) {
    extern __shared__ char sm[];
    const int tid = threadIdx.x;
    const int brow = blockIdx.x * 128;
    const int SB = K * 2 + 16;
    char* Ah = sm;
    char* Al = sm + 128 * SB;
    char* Bh = sm + 256 * SB;
    char* Bl = sm + 320 * SB;
    const int ku4 = K >> 3;

    for (int idx = tid; idx < 128 * ku4; idx += 512) {
        int r = idx / ku4, c = idx % ku4;
        int gr = brow + r;
        uint4 vh = make_uint4(0, 0, 0, 0), vl = make_uint4(0, 0, 0, 0);
        if (gr < M) {
            if (Afp) {
                const float* src = &Afp[(size_t)gr * K + c * 8];
                float4 f0 = *reinterpret_cast<const float4*>(src);
                float4 f1 = *reinterpret_cast<const float4*>(src + 4);
                float fs[8] = {f0.x, f0.y, f0.z, f0.w, f1.x, f1.y, f1.z, f1.w};
                __nv_bfloat16 hs[8], ls[8];
#pragma unroll
                for (int q = 0; q < 8; q++) {
                    hs[q] = __float2bfloat16(fs[q]);
                    ls[q] = __float2bfloat16(fs[q] - __bfloat162float(hs[q]));
                }
                vh = *reinterpret_cast<uint4*>(hs);
                vl = *reinterpret_cast<uint4*>(ls);
            } else {
                vh = *reinterpret_cast<const uint4*>(&Ahi[(size_t)gr * K + c * 8]);
                vl = *reinterpret_cast<const uint4*>(&Alo[(size_t)gr * K + c * 8]);
            }
        }
        *reinterpret_cast<uint4*>(Ah + r * SB + c * 16) = vh;
        *reinterpret_cast<uint4*>(Al + r * SB + c * 16) = vl;
    }
    for (int idx = tid; idx < 64 * ku4; idx += 512) {
        int r = idx / ku4, c = idx % ku4;
        *reinterpret_cast<uint4*>(Bh + r * SB + c * 16) =
            *reinterpret_cast<const uint4*>(&Bhi[(size_t)r * K + c * 8]);
        *reinterpret_cast<uint4*>(Bl + r * SB + c * 16) =
            *reinterpret_cast<const uint4*>(&Blo[(size_t)r * K + c * 8]);
    }
    __syncthreads();

    const int wid = tid >> 5, lane = tid & 31;
    const int wm = wid >> 2, wn = wid & 3;
    const int g = lane >> 2, t = lane & 3;
    const int KC = K >> 4;

    float acc[2][2][4];
#pragma unroll
    for (int mt = 0; mt < 2; mt++)
#pragma unroll
        for (int nt = 0; nt < 2; nt++)
#pragma unroll
            for (int q = 0; q < 4; q++) acc[mt][nt][q] = 0.f;

#pragma unroll
    for (int ab = 0; ab < 3; ab++) {
        const char* A_ = (ab == 2) ? Al : Ah;
        const char* B_ = (ab == 1) ? Bl : Bh;
        for (int kc = 0; kc < KC; kc++) {
            int kb = kc * 32 + t * 4;
            uint32_t bf[2][2];
#pragma unroll
            for (int nt = 0; nt < 2; nt++) {
                int nr = wn * 16 + nt * 8 + g;
                bf[nt][0] = *reinterpret_cast<const uint32_t*>(B_ + nr * SB + kb);
                bf[nt][1] = *reinterpret_cast<const uint32_t*>(B_ + nr * SB + kb + 16);
            }
#pragma unroll
            for (int mt = 0; mt < 2; mt++) {
                int r0 = wm * 32 + mt * 16 + g;
                uint32_t a0 = *reinterpret_cast<const uint32_t*>(A_ + r0 * SB + kb);
                uint32_t a1 = *reinterpret_cast<const uint32_t*>(A_ + (r0 + 8) * SB + kb);
                uint32_t a2 = *reinterpret_cast<const uint32_t*>(A_ + r0 * SB + kb + 16);
                uint32_t a3 = *reinterpret_cast<const uint32_t*>(A_ + (r0 + 8) * SB + kb + 16);
#pragma unroll
                for (int nt = 0; nt < 2; nt++)
                    hmma(acc[mt][nt], a0, a1, a2, a3, bf[nt][0], bf[nt][1]);
            }
        }
    }

#pragma unroll
    for (int mt = 0; mt < 2; mt++) {
#pragma unroll
        for (int nt = 0; nt < 2; nt++) {
            int row = brow + wm * 32 + mt * 16 + g;
            int col = wn * 16 + nt * 8 + 2 * t;
            float v0 = acc[mt][nt][0], v1 = acc[mt][nt][1];
            float v2 = acc[mt][nt][2], v3 = acc[mt][nt][3];
            if (act) {
                v0 = fmaxf(v0, 0.f); v1 = fmaxf(v1, 0.f);
                v2 = fmaxf(v2, 0.f); v3 = fmaxf(v3, 0.f);
            }
            if (row < M)
                *reinterpret_cast<float2*>(&C[(size_t)row * 64 + col]) = make_float2(v0, v1);
            if (row + 8 < M)
                *reinterpret_cast<float2*>(&C[(size_t)(row + 8) * 64 + col]) = make_float2(v2, v3);
        }
    }
}

// ---------------- weight packing ----------------
__global__ void k_prepB(const float* __restrict__ Om, const float* __restrict__ Ws,
                        const float* __restrict__ Wfc1) {
    int i = blockIdx.x * blockDim.x + threadIdx.x;
    if (i >= HD * NC) return;
    int k = i / NC, j = i % NC;
    float v;
    if (j < 64)       v = Om[k * 64 + j] - Om[j * 64 + k];
    else if (j < 128) { int jj = j - 64; v = 0.5f * (Ws[k * 64 + jj] + Ws[jj * 64 + k]); }
    else if (j < 256) v = Wfc1[k * 128 + (j - 128)];
    else              v = Wfc1[(64 + k) * 128 + (j - 256)];
    __nv_bfloat16 hi = __float2bfloat16(v);
    __nv_bfloat16 lo = __float2bfloat16(v - __bfloat162float(hi));
    g_Bhi[(size_t)j * HD + k] = hi;
    g_Blo[(size_t)j * HD + k] = lo;
}

__global__ void k_prepW(const float* __restrict__ src, int K,
                        __nv_bfloat16* __restrict__ dhi, __nv_bfloat16* __restrict__ dlo) {
    int i = blockIdx.x * blockDim.x + threadIdx.x;
    if (i >= K * HD) return;
    int k = i / HD, n = i % HD;
    float v = src[i];
    __nv_bfloat16 hi = __float2bfloat16(v);
    dhi[(size_t)n * K + k] = hi;
    dlo[(size_t)n * K + k] = __float2bfloat16(v - __bfloat162float(hi));
}

// ---------------- graph preprocessing ----------------
__global__ void k_init() {
    int i = blockIdx.x * blockDim.x + threadIdx.x;
    if (i < Nn) { g_deg[i] = 1; g_fill[i] = 0; }
}

__global__ void k_deg(const int* __restrict__ ei) {
    int e = blockIdx.x * blockDim.x + threadIdx.x;
    if (e < Ee) atomicAdd(&g_deg[ei[Ee + e]], 1);
}

__global__ void k_dinv() {
    int n = blockIdx.x * blockDim.x + threadIdx.x;
    if (n < Nn) g_dinv[n] = rsqrtf((float)g_deg[n]);
}

__global__ void k_scan() {
    __shared__ int sh[1024];
    __shared__ int carry_s;
    int t = threadIdx.x;
    if (t == 0) carry_s = 0;
    __syncthreads();
    for (int base = 0; base < Nn; base += 1024) {
        int v = (base + t < Nn) ? g_deg[base + t] : 0;
        int x = v;
        for (int off = 1; off < 1024; off <<= 1) {
            sh[t] = x; __syncthreads();
            if (t >= off) x += sh[t - off];
            __syncthreads();
        }
        int carry = carry_s;
        if (base + t < Nn) g_off[base + t] = carry + x - v;
        __syncthreads();
        if (t == 1023) carry_s = carry + x;
        __syncthreads();
    }
    if (t == 0) g_off[Nn] = carry_s;
}

__global__ void k_fill(const int* __restrict__ ei) {
    int e = blockIdx.x * blockDim.x + threadIdx.x;
    if (e >= NEe) return;
    int r_, c_;
    if (e < Ee) { r_ = ei[e]; c_ = ei[Ee + e]; }
    else        { r_ = c_ = e - Ee; }
    int pos = g_off[c_] + atomicAdd(&g_fill[c_], 1);
    float nv = g_dinv[r_] * g_dinv[c_];
    g_csrp[pos] = make_int2(r_, __float_as_int(nv));
}

// H snapshot + bf16 split + a,b for step 0 (fused)
__global__ __launch_bounds__(256) void k_h2b_ab(const float* __restrict__ Wfv) {
    int warp = (blockIdx.x * blockDim.x + threadIdx.x) >> 5;
    int lane = threadIdx.x & 31;
    if (warp >= Nn) return;
    int n = warp;
    float h0 = g_H[n * HD + lane], h1 = g_H[n * HD + lane + 32];
    g_H0[n * HD + lane] = h0;
    g_H0[n * HD + lane + 32] = h1;
    __nv_bfloat16 hi0 = __float2bfloat16(h0);
    __nv_bfloat16 hi1 = __float2bfloat16(h1);
    g_Hhi[n * HD + lane]      = hi0;
    g_Hhi[n * HD + lane + 32] = hi1;
    g_Hlo[n * HD + lane]      = __float2bfloat16(h0 - __bfloat162float(hi0));
    g_Hlo[n * HD + lane + 32] = __float2bfloat16(h1 - __bfloat162float(hi1));
    float pa = h0 * Wfv[lane]      + h1 * Wfv[lane + 32];
    float pb = h0 * Wfv[64 + lane] + h1 * Wfv[96 + lane];
#pragma unroll
    for (int o = 16; o > 0; o >>= 1) {
        pa += __shfl_xor_sync(0xffffffffu, pa, o);
        pb += __shfl_xor_sync(0xffffffffu, pb, o);
    }
    if (lane == 0) { g_a[0][n] = pa; g_b[0][n] = pb; }
}

// ---------------- fused per-step kernel (128-thread blocks) ----------------
// node path lane mapping: lane -> columns (2*lane, 2*lane+1)
__global__ __launch_bounds__(128) void k_step(const int* __restrict__ pairs,
                                              const float* __restrict__ gum,
                                              const float* __restrict__ Wfc2,
                                              const float* __restrict__ Wfv,
                                              int l) {
    int warp = (blockIdx.x * blockDim.x + threadIdx.x) >> 5;
    int lane = threadIdx.x & 31;
    if (warp < Nn) {
        int n = warp;
        int c2 = 2 * lane;
        int beg = g_off[n], end = g_off[n + 1];
        float s0 = 0.f, s1 = 0.f;
        int i = beg;
        for (; i + 3 < end; i += 4) {
            int2 ea = __ldg(&g_csrp[i]);
            int2 eb = __ldg(&g_csrp[i + 1]);
            int2 ec = __ldg(&g_csrp[i + 2]);
            int2 ed = __ldg(&g_csrp[i + 3]);
            float wa = __int_as_float(ea.y);
            float wb = __int_as_float(eb.y);
            float wc = __int_as_float(ec.y);
            float wd = __int_as_float(ed.y);
            uint32_t ua = __ldg(reinterpret_cast<const uint32_t*>(&g_Mb[ea.x * HD + c2]));
            uint32_t ub = __ldg(reinterpret_cast<const uint32_t*>(&g_Mb[eb.x * HD + c2]));
            uint32_t uc = __ldg(reinterpret_cast<const uint32_t*>(&g_Mb[ec.x * HD + c2]));
            uint32_t ud = __ldg(reinterpret_cast<const uint32_t*>(&g_Mb[ed.x * HD + c2]));
            __nv_bfloat162 va = *reinterpret_cast<__nv_bfloat162*>(&ua);
            __nv_bfloat162 vb = *reinterpret_cast<__nv_bfloat162*>(&ub);
            __nv_bfloat162 vc = *reinterpret_cast<__nv_bfloat162*>(&uc);
            __nv_bfloat162 vd = *reinterpret_cast<__nv_bfloat162*>(&ud);
            s0 += __bfloat162float(va.x) * wa + __bfloat162float(vb.x) * wb
                + __bfloat162float(vc.x) * wc + __bfloat162float(vd.x) * wd;
            s1 += __bfloat162float(va.y) * wa + __bfloat162float(vb.y) * wb
                + __bfloat162float(vc.y) * wc + __bfloat162float(vd.y) * wd;
        }
        for (; i < end; i++) {
            int2 e = __ldg(&g_csrp[i]);
            float w = __int_as_float(e.y);
            uint32_t u = __ldg(reinterpret_cast<const uint32_t*>(&g_Mb[e.x * HD + c2]));
            __nv_bfloat162 v = *reinterpret_cast<__nv_bfloat162*>(&u);
            s0 += __bfloat162float(v.x) * w;
            s1 += __bfloat162float(v.y) * w;
        }
        float2 av = *reinterpret_cast<const float2*>(&g_C[(size_t)n * NC + c2]);
        float dh0 = fmaxf(tanhf(s0 - fmaxf(av.x, 0.f)), 0.f);
        float dh1 = fmaxf(tanhf(s1 - fmaxf(av.y, 0.f)), 0.f);
        __nv_bfloat162 dv;
        dv.x = __float2bfloat16(dh0);
        dv.y = __float2bfloat16(dh1);
        *reinterpret_cast<__nv_bfloat162*>(&g_dHall[(size_t)l * Nn * HD + n * HD + c2]) = dv;
        float2 hv = *reinterpret_cast<const float2*>(&g_H[n * HD + c2]);
        float hn0 = hv.x + dh0;
        float hn1 = hv.y + dh1;
        *reinterpret_cast<float2*>(&g_H[n * HD + c2]) = make_float2(hn0, hn1);
        __nv_bfloat16 hi0 = __float2bfloat16(hn0);
        __nv_bfloat16 hi1 = __float2bfloat16(hn1);
        __nv_bfloat162 hiv; hiv.x = hi0; hiv.y = hi1;
        __nv_bfloat162 lov;
        lov.x = __float2bfloat16(hn0 - __bfloat162float(hi0));
        lov.y = __float2bfloat16(hn1 - __bfloat162float(hi1));
        *reinterpret_cast<__nv_bfloat162*>(&g_Hhi[n * HD + c2]) = hiv;
        *reinterpret_cast<__nv_bfloat162*>(&g_Hlo[n * HD + c2]) = lov;
        float pa = hn0 * Wfv[c2]      + hn1 * Wfv[c2 + 1];
        float pb = hn0 * Wfv[64 + c2] + hn1 * Wfv[64 + c2 + 1];
#pragma unroll
        for (int o = 16; o > 0; o >>= 1) {
            pa += __shfl_xor_sync(0xffffffffu, pa, o);
            pb += __shfl_xor_sync(0xffffffffu, pb, o);
        }
        if (lane == 0) { g_a[(l + 1) & 1][n] = pa; g_b[(l + 1) & 1][n] = pb; }
    } else {
        // ---- pair path ----
        int p = warp - Nn;
        if (p >= Pp) return;
        int s = pairs[2 * p], d = pairs[2 * p + 1];
        const float* Us = &g_C[(size_t)s * NC + 128];
        const float* Vd = &g_C[(size_t)d * NC + 256];
        float l0 = 0.f, l1 = 0.f;
#pragma unroll
        for (int i = 0; i < 4; i++) {
            int j = lane + 32 * i;
            float hv = fmaxf(__ldg(&Us[j]) + __ldg(&Vd[j]), 0.f);
            l0 += hv * Wfc2[2 * j];
            l1 += hv * Wfc2[2 * j + 1];
        }
#pragma unroll
        for (int o = 16; o > 0; o >>= 1) {
            l0 += __shfl_xor_sync(0xffffffffu, l0, o);
            l1 += __shfl_xor_sync(0xffffffffu, l1, o);
        }
        if (lane == 0) {
            int ph = l & 1;
            float z  = g_a[ph][s] + g_b[ph][d];
            float nu = fmaxf(z, 0.f) + log1pf(expf(-fabsf(z))) + 1.0f;
            float g0 = __ldg(&gum[((size_t)l * Pp + p) * 2]);
            float g1 = __ldg(&gum[((size_t)l * Pp + p) * 2 + 1]);
            float diff = ((l1 + g1) - (l0 + g0)) / nu;
            g_tau[(size_t)l * Pp + p] = 1.f / (1.f + expf(diff));
        }
    }
}

// ---------------- final: assemble r -> bf16 hi/lo, write ts ----------------
__global__ __launch_bounds__(256) void k_final(const int* __restrict__ pairs,
                                               float* __restrict__ out) {
    int warp = (blockIdx.x * blockDim.x + threadIdx.x) >> 5;
    int lane = threadIdx.x & 31;
    if (warp >= Pp) return;
    int p = warp;
    int s = pairs[2 * p], d = pairs[2 * p + 1];
    float2 hs = *reinterpret_cast<const float2*>(&g_H0[s * HD + 2 * lane]);
    float2 hd = *reinterpret_cast<const float2*>(&g_H0[d * HD + 2 * lane]);
    float r0 = hs.x, r1 = hs.y;
    float r2 = hd.x, r3 = hd.y;
    float tval = (lane < Ll) ? g_tau[(size_t)lane * Pp + p] : 0.f;
    float ts = 0.f;
#pragma unroll
    for (int l = 0; l < Ll; l++) {
        float tau = __shfl_sync(0xffffffffu, tval, l);
        const __nv_bfloat16* slab = &g_dHall[(size_t)l * Nn * HD];
        __nv_bfloat162 ds = *reinterpret_cast<const __nv_bfloat162*>(&slab[s * HD + 2 * lane]);
        __nv_bfloat162 dd = *reinterpret_cast<const __nv_bfloat162*>(&slab[d * HD + 2 * lane]);
        r0 += tau * __bfloat162float(ds.x);
        r1 += tau * __bfloat162float(ds.y);
        r2 += tau * __bfloat162float(dd.x);
        r3 += tau * __bfloat162float(dd.y);
        ts += tau;
    }
    size_t base = (size_t)p * 2 * HD;
    __nv_bfloat16 h0 = __float2bfloat16(r0);
    __nv_bfloat16 h1 = __float2bfloat16(r1);
    __nv_bfloat16 h2 = __float2bfloat16(r2);
    __nv_bfloat16 h3 = __float2bfloat16(r3);
    __nv_bfloat162 lo01, lo23;
    lo01.x = __float2bfloat16(r0 - __bfloat162float(h0));
    lo01.y = __float2bfloat16(r1 - __bfloat162float(h1));
    lo23.x = __float2bfloat16(r2 - __bfloat162float(h2));
    lo23.y = __float2bfloat16(r3 - __bfloat162float(h3));
    __nv_bfloat162 hi01; hi01.x = h0; hi01.y = h1;
    __nv_bfloat162 hi23; hi23.x = h2; hi23.y = h3;
    *reinterpret_cast<__nv_bfloat162*>(&g_rhi[base + 2 * lane]) = hi01;
    *reinterpret_cast<__nv_bfloat162*>(&g_rhi[base + HD + 2 * lane]) = hi23;
    *reinterpret_cast<__nv_bfloat162*>(&g_rlo[base + 2 * lane]) = lo01;
    *reinterpret_cast<__nv_bfloat162*>(&g_rlo[base + HD + 2 * lane]) = lo23;
    if (lane == 0) out[Pp + p] = ts;
}

// ---------------- final scores ----------------
__global__ __launch_bounds__(256) void k_score(const float* __restrict__ Wp2,
                                               float* __restrict__ out) {
    int warp = (blockIdx.x * blockDim.x + threadIdx.x) >> 5;
    int lane = threadIdx.x & 31;
    if (warp >= Pp) return;
    int p = warp;
    float t0 = g_C[(size_t)p * 64 + 2 * lane];
    float t1 = g_C[(size_t)p * 64 + 2 * lane + 1];
    float acc = t0 * Wp2[2 * lane] + t1 * Wp2[2 * lane + 1];
#pragma unroll
    for (int o = 16; o > 0; o >>= 1) acc += __shfl_xor_sync(0xffffffffu, acc, o);
    if (lane == 0) out[p] = acc;
}

// ---------------- host ----------------
extern "C" void kernel_launch(void* const* d_in, const int* in_sizes, int n_in,
                              void* d_out, int out_size) {
    const float* x    = (const float*)d_in[0];
    const int*   ei   = (const int*)d_in[1];
    const int*   pairs= (const int*)d_in[2];
    const float* gum  = (const float*)d_in[3];
    const float* Wenc = (const float*)d_in[4];
    const float* Om   = (const float*)d_in[5];
    const float* Wsr  = (const float*)d_in[6];
    const float* Wfc1 = (const float*)d_in[7];
    const float* Wfc2 = (const float*)d_in[8];
    const float* Wfv  = (const float*)d_in[9];
    const float* Wp1  = (const float*)d_in[10];
    const float* Wp2  = (const float*)d_in[11];
    float* out = (float*)d_out;

    void *pH, *pC, *pHhi, *pHlo, *pWeh, *pWel, *pWph, *pWpl, *pRhi, *pRlo;
    cudaGetSymbolAddress(&pH, g_H);
    cudaGetSymbolAddress(&pC, g_C);
    cudaGetSymbolAddress(&pHhi, g_Hhi);
    cudaGetSymbolAddress(&pHlo, g_Hlo);
    cudaGetSymbolAddress(&pWeh, g_Wehi);
    cudaGetSymbolAddress(&pWel, g_Welo);
    cudaGetSymbolAddress(&pWph, g_Wp1hi);
    cudaGetSymbolAddress(&pWpl, g_Wp1lo);
    cudaGetSymbolAddress(&pRhi, g_rhi);
    cudaGetSymbolAddress(&pRlo, g_rlo);
    float* H_ = (float*)pH;
    float* C_ = (float*)pC;
    const __nv_bfloat16* Hhi_ = (const __nv_bfloat16*)pHhi;
    const __nv_bfloat16* Hlo_ = (const __nv_bfloat16*)pHlo;

    cudaFuncSetAttribute(mma_step, cudaFuncAttributeMaxDynamicSharedMemorySize, S_TOT);
    const int SM64 = 384 * (INF * 2 + 16);
    cudaFuncSetAttribute(mma_gemm64, cudaFuncAttributeMaxDynamicSharedMemorySize, SM64);

    // side stream for graph preprocessing — fork from capture stream
    cudaStream_t s1;
    cudaStreamCreateWithFlags(&s1, cudaStreamNonBlocking);
    cudaEvent_t evFork, evPrep;
    cudaEventCreateWithFlags(&evFork, cudaEventDisableTiming);
    cudaEventCreateWithFlags(&evPrep, cudaEventDisableTiming);

    cudaEventRecord(evFork, 0);
    cudaStreamWaitEvent(s1, evFork, 0);

    // ---- graph prep on s1 ----
    k_init<<<(Nn + 255) / 256, 256, 0, s1>>>();
    k_deg<<<(Ee + 255) / 256, 256, 0, s1>>>(ei);
    k_dinv<<<(Nn + 255) / 256, 256, 0, s1>>>();
    k_scan<<<1, 1024, 0, s1>>>();
    k_fill<<<(NEe + 255) / 256, 256, 0, s1>>>(ei);
    cudaEventRecord(evPrep, s1);

    // ---- dense prologue on stream 0 ----
    k_prepB<<<(HD * NC + 255) / 256, 256>>>(Om, Wsr, Wfc1);
    k_prepW<<<(INF * HD + 255) / 256, 256>>>(Wenc, INF, (__nv_bfloat16*)pWeh, (__nv_bfloat16*)pWel);
    k_prepW<<<(INF * HD + 255) / 256, 256>>>(Wp1, INF, (__nv_bfloat16*)pWph, (__nv_bfloat16*)pWpl);
    mma_gemm64<<<(Nn + 127) / 128, 512, SM64>>>(
        x, nullptr, nullptr,
        (const __nv_bfloat16*)pWeh, (const __nv_bfloat16*)pWel, H_, Nn, INF, 1);
    k_h2b_ab<<<(Nn * 32 + 255) / 256, 256>>>(Wfv);

    dim3 grid_mma((Nn + 127) / 128, 2);
    int step_blocks = ((Nn + Pp) * 32 + 127) / 128;
    for (int l = 0; l < Ll; l++) {
        mma_step<<<grid_mma, 512, S_TOT>>>(Hhi_, Hlo_);
        if (l == 0) cudaStreamWaitEvent(0, evPrep, 0);
        k_step<<<step_blocks, 128>>>(pairs, gum, Wfc2, Wfv, l);
    }

    // r (bf16 hi/lo) + ts, then T = relu(r @ Wp1) via HMMA, then scores
    k_final<<<(Pp * 32 + 255) / 256, 256>>>(pairs, out);
    mma_gemm64<<<(Pp + 127) / 128, 512, SM64>>>(
        nullptr, (const __nv_bfloat16*)pRhi, (const __nv_bfloat16*)pRlo,
        (const __nv_bfloat16*)pWph, (const __nv_bfloat16*)pWpl, C_, Pp, INF, 1);
    k_score<<<(Pp * 32 + 255) / 256, 256>>>(Wp2, out);

    cudaStreamDestroy(s1);
    cudaEventDestroy(evFork);
    cudaEventDestroy(evPrep);
}